// round 10
// baseline (speedup 1.0000x reference)
#include <cuda_runtime.h>
#include <cstdint>

#define C_DIM   1024
#define NSEQ    2048
#define NHEADS  16
#define HDIM    64
#define BATCH   2
#define ROWS    (BATCH * NSEQ)       // 4096
#define ATT_SCALE 0.125f             // 1/sqrt(64)

// Scratch (no allocations allowed in kernel_launch)
__device__ float g_qkv[ROWS * 3 * C_DIM];       // [4096, 3072] (tf32-rounded)
__device__ float g_att[ROWS * C_DIM];           // [4096, 1024] (tf32-rounded)
__device__ float g_xtf[ROWS * C_DIM];           // x, tf32-rounded
__device__ float g_wqkv_tf[3 * C_DIM * C_DIM];  // w_qkv, tf32-rounded
__device__ float g_wproj_tf[C_DIM * C_DIM];     // w_proj, tf32-rounded

// ===========================================================================
// helpers (arch-independent PTX)
// ===========================================================================
__device__ __forceinline__ uint32_t f2tf32(float x) {
    uint32_t r;
    asm("cvt.rna.tf32.f32 %0, %1;" : "=r"(r) : "f"(x));
    return r;
}
__device__ __forceinline__ uint32_t smem_u32(const void* p) {
    uint32_t a;
    asm("{ .reg .u64 t; cvta.to.shared.u64 t, %1; cvt.u32.u64 %0, t; }"
        : "=r"(a) : "l"(p));
    return a;
}
__device__ __forceinline__ void ldsm_x4(uint32_t addr, uint32_t* d) {
    asm volatile("ldmatrix.sync.aligned.m8n8.x4.shared.b16 {%0,%1,%2,%3}, [%4];"
                 : "=r"(d[0]), "=r"(d[1]), "=r"(d[2]), "=r"(d[3]) : "r"(addr));
}
__device__ __forceinline__ void mma_tf32(float* d, const uint32_t* a, const uint32_t* b) {
    asm volatile(
        "mma.sync.aligned.m16n8k8.row.col.f32.tf32.tf32.f32 "
        "{%0,%1,%2,%3}, {%4,%5,%6,%7}, {%8,%9}, {%0,%1,%2,%3};"
        : "+f"(d[0]), "+f"(d[1]), "+f"(d[2]), "+f"(d[3])
        : "r"(a[0]), "r"(a[1]), "r"(a[2]), "r"(a[3]), "r"(b[0]), "r"(b[1]));
}
#define CP16(dst, src) \
    asm volatile("cp.async.cg.shared.global [%0], [%1], 16;" \
                 :: "r"(dst), "l"(src) : "memory")
#define CP_COMMIT() asm volatile("cp.async.commit_group;" ::: "memory")
#define CP_WAIT1()  asm volatile("cp.async.wait_group 1;" ::: "memory")
#define CP_WAIT0()  asm volatile("cp.async.wait_group 0;" ::: "memory")

// ===========================================================================
// Merged pre-pass: round three arrays fp32 -> tf32-in-fp32 (rna).
// ===========================================================================
__global__ void cvt3_tf32(const float* a, float* oa, int na4,
                          const float* b, float* ob, int nb4,
                          const float* c, float* oc, int nc4)
{
    int i = blockIdx.x * blockDim.x + threadIdx.x;
    int stride = gridDim.x * blockDim.x;
    int tot = na4 + nb4 + nc4;
    for (; i < tot; i += stride) {
        const float4* src;
        uint4* dst;
        int k = i;
        if (k < na4) { src = (const float4*)a + k; dst = (uint4*)oa + k; }
        else if ((k -= na4) < nb4) { src = (const float4*)b + k; dst = (uint4*)ob + k; }
        else { k -= nb4; src = (const float4*)c + k; dst = (uint4*)oc + k; }
        float4 v = *src;
        *dst = make_uint4(f2tf32(v.x), f2tf32(v.y), f2tf32(v.z), f2tf32(v.w));
    }
}

// ===========================================================================
// tf32 mma.sync NT GEMM, 64x64 warp tiles:
// C[M,Nt] = A[M,K] @ W[Nt,K]^T + bias[Nt].  Inputs pre-rounded tf32.
// Block tile 256(M) x 128(N), BK=32, 256 threads = 8 warps (4m x 2n),
// each warp 64x64 -> per ks: 8 LDSM / 32 HMMA (ratio 4).
// 3-stage cp.async ring; pitch 36 floats; 1 CTA/SM (162KB smem).
// Staging: A rows 0..255, B rows 256..383 (contiguous, same pitch).
// ===========================================================================
#define GP 36
#define GSTG (384 * GP)                  // floats per stage (A 256 + B 128 rows)
#define GEMM_SMEM (3 * GSTG * 4)         // 165888 B

__global__ __launch_bounds__(256, 1)
void gemm_mma_tf32(const float* __restrict__ A, const float* __restrict__ W,
                   const float* __restrict__ bias, float* __restrict__ Cout,
                   int M, int Nt, int K, int round_out)
{
    extern __shared__ float smf[];
    const uint32_t smb = smem_u32(smf);
    const int t      = threadIdx.x;
    const int lane   = t & 31;
    const int r      = lane >> 2;
    const int cq     = lane & 3;
    const int g      = lane >> 3;
    const int j      = lane & 7;
    const int wid    = t >> 5;
    const int warp_m = wid & 3;     // 4 warps over M (64 rows each)
    const int warp_n = wid >> 2;    // 2 warps over N (64 cols each)
    const int m0 = blockIdx.y << 8;
    const int n0 = blockIdx.x << 7;

    // ldmatrix per-lane base offsets (bytes, within a stage)
    const uint32_t a_lane = (uint32_t)(((warp_m * 64 + (g & 1) * 8 + j) * GP
                                        + (g >> 1) * 4) * 4);
    const uint32_t b_lane = (uint32_t)(((256 + warp_n * 64 + (g >> 1) * 8 + j) * GP
                                        + (g & 1) * 4) * 4);

    const int grow = t >> 3;              // 0..31 (x12 via p)
    const int gc4  = (t & 7) << 2;        // 0..28

    // cp.async issue of one BK=32 chunk into stage s.
    // rows 0..255 = A tile rows, rows 256..383 = B (W) tile rows.
#define ISSUE_CHUNK(cidx, s)                                                   \
    {                                                                          \
        const float* Ap = A + (size_t)m0 * K + (cidx) * 32;                    \
        const float* Wp = W + (size_t)n0 * K + (cidx) * 32;                    \
        const uint32_t sb = smb + (uint32_t)((s) * GSTG * 4);                  \
        _Pragma("unroll")                                                      \
        for (int p = 0; p < 12; p++) {                                         \
            int row = grow + p * 32;                                           \
            const float* src = (row < 256)                                     \
                ? Ap + (size_t)row * K + gc4                                   \
                : Wp + (size_t)(row - 256) * K + gc4;                          \
            CP16(sb + (uint32_t)((row * GP + gc4) * 4), src);                  \
        }                                                                      \
        CP_COMMIT();                                                           \
    }

    float acc[4][8][4];
#pragma unroll
    for (int i = 0; i < 4; i++)
#pragma unroll
        for (int jj = 0; jj < 8; jj++)
#pragma unroll
            for (int e = 0; e < 4; e++) acc[i][jj][e] = 0.f;

    const int nch = K / 32;
    ISSUE_CHUNK(0, 0);
    ISSUE_CHUNK(1, 1);

    int stage = 0;
    for (int c = 0; c < nch; c++) {
        if (c + 1 < nch) CP_WAIT1(); else CP_WAIT0();
        __syncthreads();
        if (c + 2 < nch) {
            int ns = stage + 2; if (ns >= 3) ns -= 3;
            ISSUE_CHUNK(c + 2, ns);
        }

        const uint32_t sbase = smb + (uint32_t)(stage * GSTG * 4);
#pragma unroll
        for (int ks = 0; ks < 4; ks++) {
            uint32_t afr[4][4], bfr[8][2];
#pragma unroll
            for (int mt = 0; mt < 4; mt++)
                ldsm_x4(sbase + a_lane + (uint32_t)((mt * 16 * GP + ks * 8) * 4),
                        afr[mt]);
#pragma unroll
            for (int p = 0; p < 4; p++) {
                uint32_t q[4];
                ldsm_x4(sbase + b_lane + (uint32_t)((p * 16 * GP + ks * 8) * 4), q);
                bfr[2 * p][0] = q[0]; bfr[2 * p][1] = q[1];
                bfr[2 * p + 1][0] = q[2]; bfr[2 * p + 1][1] = q[3];
            }
#pragma unroll
            for (int mt = 0; mt < 4; mt++)
#pragma unroll
                for (int nt = 0; nt < 8; nt++)
                    mma_tf32(acc[mt][nt], afr[mt], bfr[nt]);
        }
        if (++stage == 3) stage = 0;
        __syncthreads();
    }

    // Epilogue: bias, optional tf32 rounding, direct stores
    const int c2 = cq << 1;
#pragma unroll
    for (int nt = 0; nt < 8; nt++) {
        const int gn = n0 + warp_n * 64 + nt * 8 + c2;
        const float b0 = bias[gn], b1 = bias[gn + 1];
#pragma unroll
        for (int mt = 0; mt < 4; mt++) {
            const int gm = m0 + warp_m * 64 + mt * 16 + r;
            float2 v0, v1;
            v0.x = acc[mt][nt][0] + b0; v0.y = acc[mt][nt][1] + b1;
            v1.x = acc[mt][nt][2] + b0; v1.y = acc[mt][nt][3] + b1;
            if (round_out) {
                v0.x = __uint_as_float(f2tf32(v0.x));
                v0.y = __uint_as_float(f2tf32(v0.y));
                v1.x = __uint_as_float(f2tf32(v1.x));
                v1.y = __uint_as_float(f2tf32(v1.y));
            }
            *(float2*)&Cout[(size_t)gm * Nt + gn]       = v0;
            *(float2*)&Cout[(size_t)(gm + 8) * Nt + gn] = v1;
        }
    }
#undef ISSUE_CHUNK
}

// ===========================================================================
// Flash attention (R9 version -- measured 181 TF/s): tf32 mma.sync,
// 32-query warps, cp.async 3-stage K/V ring, ldmatrix Q/K frags,
// k-perm PV register reuse. AQ=256, 256 threads = 8 warps x 32 rows.
// ===========================================================================
#define AQ      256
#define AP      68
#define KSTG    (2 * 64 * AP)                 // K+V one stage (floats)
#define OFF_KV  (AQ * AP)
#define ATTN_SMEM ((AQ * AP + 3 * KSTG) * 4)  // 174080 B

__global__ __launch_bounds__(256, 1)
void attn_mma(const float* __restrict__ qkv, float* __restrict__ out)
{
    extern __shared__ float sm[];
    const uint32_t smb = smem_u32(sm);
    const int t    = threadIdx.x;
    const int lane = t & 31;
    const int wid  = t >> 5;
    const int r    = lane >> 2;
    const int cq   = lane & 3;
    const int g    = lane >> 3;
    const int j    = lane & 7;
    const int q0   = blockIdx.x * AQ;
    const int b    = blockIdx.y >> 4;
    const int h    = blockIdx.y & 15;
    const int rs   = 3 * C_DIM;

    const float* qb = qkv + ((size_t)(b * NSEQ + q0) * 3) * C_DIM + h * HDIM;
    const float* kb = qkv + ((size_t)(b * NSEQ) * 3 + 1) * C_DIM + h * HDIM;
    const float* vb = qkv + ((size_t)(b * NSEQ) * 3 + 2) * C_DIM + h * HDIM;

    const int wrow = wid * 32;   // warp's query-row base (32 rows)

    const uint32_t q_lane = (uint32_t)(((wrow + (g & 1) * 8 + j) * AP
                                        + (g >> 1) * 4) * 4);
    const uint32_t k_lane = (uint32_t)((((g >> 1) * 8 + j) * AP
                                        + (g & 1) * 4) * 4);

    const int srow = t >> 4;              // 0..15 (x4 via p)
    const int sd4  = (t & 15) << 2;

    // ---- Q via cp.async (group 0) ----
#pragma unroll
    for (int p = 0; p < 16; p++) {
        int row = srow + p * 16;
        CP16(smb + (uint32_t)((row * AP + sd4) * 4), qb + (size_t)row * rs + sd4);
    }
    CP_COMMIT();

#define ISSUE_KV(kt, s)                                                        \
    {                                                                          \
        const float* kn = kb + (size_t)((kt) * 64) * rs;                       \
        const float* vn = vb + (size_t)((kt) * 64) * rs;                       \
        const uint32_t sb = smb + (uint32_t)((OFF_KV + (s) * KSTG) * 4);       \
        _Pragma("unroll")                                                      \
        for (int p = 0; p < 4; p++) {                                          \
            int row = srow + p * 16;                                           \
            CP16(sb + (uint32_t)((row * AP + sd4) * 4),                        \
                 kn + (size_t)row * rs + sd4);                                 \
            CP16(sb + (uint32_t)((64 * AP + row * AP + sd4) * 4),              \
                 vn + (size_t)row * rs + sd4);                                 \
        }                                                                      \
        CP_COMMIT();                                                           \
    }

    ISSUE_KV(0, 0);
    ISSUE_KV(1, 1);

    float o_[2][8][4];
#pragma unroll
    for (int mt = 0; mt < 2; mt++)
#pragma unroll
        for (int nt = 0; nt < 8; nt++)
#pragma unroll
            for (int e = 0; e < 4; e++) o_[mt][nt][e] = 0.f;
    float m_r[2][2], l_r[2][2];
#pragma unroll
    for (int mt = 0; mt < 2; mt++) {
        m_r[mt][0] = -1e30f; m_r[mt][1] = -1e30f;
        l_r[mt][0] = 0.f;    l_r[mt][1] = 0.f;
    }

    const int NT = NSEQ / 64;
    int stage = 0;
    for (int kt = 0; kt < NT; kt++) {
        if (kt + 1 < NT) CP_WAIT1(); else CP_WAIT0();
        __syncthreads();
        if (kt + 2 < NT) {
            int ns = stage + 2; if (ns >= 3) ns -= 3;
            ISSUE_KV(kt + 2, ns);
        }

        const uint32_t kbase = smb + (uint32_t)((OFF_KV + stage * KSTG) * 4);
        const float*   Vst   = &sm[OFF_KV + stage * KSTG + 64 * AP];

        // ---- S = Q @ K^T (warp: 32 rows x 64 cols) ----
        float s_[2][8][4];
#pragma unroll
        for (int mt = 0; mt < 2; mt++)
#pragma unroll
            for (int nt = 0; nt < 8; nt++)
#pragma unroll
                for (int e = 0; e < 4; e++) s_[mt][nt][e] = 0.f;

#pragma unroll
        for (int ks = 0; ks < 8; ks++) {
            uint32_t aq[2][4];
            ldsm_x4(smb + q_lane + (uint32_t)(ks * 32), aq[0]);
            ldsm_x4(smb + q_lane + (uint32_t)(16 * AP * 4 + ks * 32), aq[1]);
#pragma unroll
            for (int p = 0; p < 4; p++) {
                uint32_t qv[4];
                ldsm_x4(kbase + k_lane + (uint32_t)((p * 16 * AP) * 4 + ks * 32), qv);
                uint32_t b0[2] = {qv[0], qv[1]};
                uint32_t b1[2] = {qv[2], qv[3]};
                mma_tf32(s_[0][2 * p],     aq[0], b0);
                mma_tf32(s_[0][2 * p + 1], aq[0], b1);
                mma_tf32(s_[1][2 * p],     aq[1], b0);
                mma_tf32(s_[1][2 * p + 1], aq[1], b1);
            }
        }

        // ---- online softmax ----
#pragma unroll
        for (int mt = 0; mt < 2; mt++) {
            float ml0 = -1e30f, ml1 = -1e30f;
#pragma unroll
            for (int nt = 0; nt < 8; nt++) {
                s_[mt][nt][0] *= ATT_SCALE; s_[mt][nt][1] *= ATT_SCALE;
                s_[mt][nt][2] *= ATT_SCALE; s_[mt][nt][3] *= ATT_SCALE;
                ml0 = fmaxf(ml0, fmaxf(s_[mt][nt][0], s_[mt][nt][1]));
                ml1 = fmaxf(ml1, fmaxf(s_[mt][nt][2], s_[mt][nt][3]));
            }
            ml0 = fmaxf(ml0, __shfl_xor_sync(0xffffffffu, ml0, 1));
            ml0 = fmaxf(ml0, __shfl_xor_sync(0xffffffffu, ml0, 2));
            ml1 = fmaxf(ml1, __shfl_xor_sync(0xffffffffu, ml1, 1));
            ml1 = fmaxf(ml1, __shfl_xor_sync(0xffffffffu, ml1, 2));

            float mn0 = fmaxf(m_r[mt][0], ml0), mn1 = fmaxf(m_r[mt][1], ml1);
            float cr0 = __expf(m_r[mt][0] - mn0), cr1 = __expf(m_r[mt][1] - mn1);
            m_r[mt][0] = mn0; m_r[mt][1] = mn1;

            float rs0 = 0.f, rs1 = 0.f;
#pragma unroll
            for (int nt = 0; nt < 8; nt++) {
                s_[mt][nt][0] = __expf(s_[mt][nt][0] - mn0);
                s_[mt][nt][1] = __expf(s_[mt][nt][1] - mn0);
                s_[mt][nt][2] = __expf(s_[mt][nt][2] - mn1);
                s_[mt][nt][3] = __expf(s_[mt][nt][3] - mn1);
                rs0 += s_[mt][nt][0] + s_[mt][nt][1];
                rs1 += s_[mt][nt][2] + s_[mt][nt][3];
            }
            rs0 += __shfl_xor_sync(0xffffffffu, rs0, 1);
            rs0 += __shfl_xor_sync(0xffffffffu, rs0, 2);
            rs1 += __shfl_xor_sync(0xffffffffu, rs1, 1);
            rs1 += __shfl_xor_sync(0xffffffffu, rs1, 2);
            l_r[mt][0] = l_r[mt][0] * cr0 + rs0;
            l_r[mt][1] = l_r[mt][1] * cr1 + rs1;

#pragma unroll
            for (int nt = 0; nt < 8; nt++) {
                o_[mt][nt][0] *= cr0; o_[mt][nt][1] *= cr0;
                o_[mt][nt][2] *= cr1; o_[mt][nt][3] *= cr1;
            }
        }

        // ---- O += P @ V : P straight from s_ registers (k-perm) ----
#pragma unroll
        for (int ks = 0; ks < 8; ks++) {
            uint32_t a0[4], a1[4];
            a0[0] = f2tf32(s_[0][ks][0]); a0[1] = f2tf32(s_[0][ks][2]);
            a0[2] = f2tf32(s_[0][ks][1]); a0[3] = f2tf32(s_[0][ks][3]);
            a1[0] = f2tf32(s_[1][ks][0]); a1[1] = f2tf32(s_[1][ks][2]);
            a1[2] = f2tf32(s_[1][ks][1]); a1[3] = f2tf32(s_[1][ks][3]);
            const float* Vb = Vst + (ks * 8 + 2 * cq) * AP + r;
#pragma unroll
            for (int nt = 0; nt < 8; nt++) {
                uint32_t bf[2];
                bf[0] = __float_as_uint(Vb[nt * 8]);
                bf[1] = __float_as_uint(Vb[nt * 8 + AP]);
                mma_tf32(o_[0][nt], a0, bf);
                mma_tf32(o_[1][nt], a1, bf);
            }
        }

        if (++stage == 3) stage = 0;
        __syncthreads();
    }

    // ---- epilogue: normalize, round to tf32 (feeds proj gemm), store ----
#pragma unroll
    for (int mt = 0; mt < 2; mt++) {
        const float i0 = 1.f / l_r[mt][0], i1 = 1.f / l_r[mt][1];
        const int row0 = b * NSEQ + q0 + wrow + mt * 16 + r;
#pragma unroll
        for (int nt = 0; nt < 8; nt++) {
            const int col = h * HDIM + nt * 8 + 2 * cq;
            float2 v0, v1;
            v0.x = __uint_as_float(f2tf32(o_[mt][nt][0] * i0));
            v0.y = __uint_as_float(f2tf32(o_[mt][nt][1] * i0));
            v1.x = __uint_as_float(f2tf32(o_[mt][nt][2] * i1));
            v1.y = __uint_as_float(f2tf32(o_[mt][nt][3] * i1));
            *(float2*)&out[(size_t)row0 * C_DIM + col]       = v0;
            *(float2*)&out[(size_t)(row0 + 8) * C_DIM + col] = v1;
        }
    }
#undef ISSUE_KV
}

// ---------------------------------------------------------------------------
extern "C" void kernel_launch(void* const* d_in, const int* in_sizes, int n_in,
                              void* d_out, int out_size)
{
    const float* x      = (const float*)d_in[0];
    const float* w_qkv  = (const float*)d_in[1];
    const float* b_qkv  = (const float*)d_in[2];
    const float* w_proj = (const float*)d_in[3];
    const float* b_proj = (const float*)d_in[4];
    float* out = (float*)d_out;

    float *qkv_s, *att_s, *xtf, *wqtf, *wptf;
    cudaGetSymbolAddress((void**)&qkv_s, g_qkv);
    cudaGetSymbolAddress((void**)&att_s, g_att);
    cudaGetSymbolAddress((void**)&xtf,   g_xtf);
    cudaGetSymbolAddress((void**)&wqtf,  g_wqkv_tf);
    cudaGetSymbolAddress((void**)&wptf,  g_wproj_tf);

    cudaFuncSetAttribute(gemm_mma_tf32, cudaFuncAttributeMaxDynamicSharedMemorySize, GEMM_SMEM);
    cudaFuncSetAttribute(attn_mma, cudaFuncAttributeMaxDynamicSharedMemorySize, ATTN_SMEM);

    // 0) Pre-round inputs to tf32 (single merged launch)
    cvt3_tf32<<<1184, 256>>>(x, xtf, ROWS * C_DIM / 4,
                             w_qkv, wqtf, 3 * C_DIM * C_DIM / 4,
                             w_proj, wptf, C_DIM * C_DIM / 4);

    // 1) QKV projection -> tf32-rounded [4096,3072]
    dim3 g1(3 * C_DIM / 128, ROWS / 256);
    gemm_mma_tf32<<<g1, 256, GEMM_SMEM>>>(xtf, wqtf, b_qkv, qkv_s,
                                          ROWS, 3 * C_DIM, C_DIM, 1);

    // 2) Fused attention -> tf32-rounded [4096,1024]
    dim3 g2(NSEQ / AQ, BATCH * NHEADS);
    attn_mma<<<g2, 256, ATTN_SMEM>>>(qkv_s, att_s);

    // 3) Output projection -> fp32 out
    dim3 g3(C_DIM / 128, ROWS / 256);
    gemm_mma_tf32<<<g3, 256, GEMM_SMEM>>>(att_s, wptf, b_proj, out,
                                          ROWS, C_DIM, C_DIM, 0);
}

// round 12
// speedup vs baseline: 1.0240x; 1.0240x over previous
#include <cuda_runtime.h>
#include <cstdint>

#define C_DIM   1024
#define NSEQ    2048
#define NHEADS  16
#define HDIM    64
#define BATCH   2
#define ROWS    (BATCH * NSEQ)       // 4096
#define ATT_SCALE 0.125f             // 1/sqrt(64)

// Scratch (no allocations allowed in kernel_launch)
__device__ float g_qkv[ROWS * 3 * C_DIM];       // [4096, 3072] (tf32-rounded)
__device__ float g_att[ROWS * C_DIM];           // [4096, 1024] (tf32-rounded)
__device__ float g_xtf[ROWS * C_DIM];           // x, tf32-rounded
__device__ float g_wqkv_tf[3 * C_DIM * C_DIM];  // w_qkv, tf32-rounded
__device__ float g_wproj_tf[C_DIM * C_DIM];     // w_proj, tf32-rounded

// ===========================================================================
// helpers (arch-independent PTX)
// ===========================================================================
__device__ __forceinline__ uint32_t f2tf32(float x) {
    uint32_t r;
    asm("cvt.rna.tf32.f32 %0, %1;" : "=r"(r) : "f"(x));
    return r;
}
__device__ __forceinline__ uint32_t smem_u32(const void* p) {
    uint32_t a;
    asm("{ .reg .u64 t; cvta.to.shared.u64 t, %1; cvt.u32.u64 %0, t; }"
        : "=r"(a) : "l"(p));
    return a;
}
__device__ __forceinline__ void ldsm_x4(uint32_t addr, uint32_t* d) {
    asm volatile("ldmatrix.sync.aligned.m8n8.x4.shared.b16 {%0,%1,%2,%3}, [%4];"
                 : "=r"(d[0]), "=r"(d[1]), "=r"(d[2]), "=r"(d[3]) : "r"(addr));
}
__device__ __forceinline__ void mma_tf32(float* d, const uint32_t* a, const uint32_t* b) {
    asm volatile(
        "mma.sync.aligned.m16n8k8.row.col.f32.tf32.tf32.f32 "
        "{%0,%1,%2,%3}, {%4,%5,%6,%7}, {%8,%9}, {%0,%1,%2,%3};"
        : "+f"(d[0]), "+f"(d[1]), "+f"(d[2]), "+f"(d[3])
        : "r"(a[0]), "r"(a[1]), "r"(a[2]), "r"(a[3]), "r"(b[0]), "r"(b[1]));
}
#define CP16(dst, src) \
    asm volatile("cp.async.cg.shared.global [%0], [%1], 16;" \
                 :: "r"(dst), "l"(src) : "memory")
#define CP_COMMIT() asm volatile("cp.async.commit_group;" ::: "memory")
#define CP_WAIT1()  asm volatile("cp.async.wait_group 1;" ::: "memory")
#define CP_WAIT0()  asm volatile("cp.async.wait_group 0;" ::: "memory")

// ===========================================================================
// Merged pre-pass: round three arrays fp32 -> tf32-in-fp32 (rna).
// ===========================================================================
__global__ void cvt3_tf32(const float* a, float* oa, int na4,
                          const float* b, float* ob, int nb4,
                          const float* c, float* oc, int nc4)
{
    int i = blockIdx.x * blockDim.x + threadIdx.x;
    int stride = gridDim.x * blockDim.x;
    int tot = na4 + nb4 + nc4;
    for (; i < tot; i += stride) {
        const float4* src;
        uint4* dst;
        int k = i;
        if (k < na4) { src = (const float4*)a + k; dst = (uint4*)oa + k; }
        else if ((k -= na4) < nb4) { src = (const float4*)b + k; dst = (uint4*)ob + k; }
        else { k -= nb4; src = (const float4*)c + k; dst = (uint4*)oc + k; }
        float4 v = *src;
        *dst = make_uint4(f2tf32(v.x), f2tf32(v.y), f2tf32(v.z), f2tf32(v.w));
    }
}

// ===========================================================================
// tf32 mma.sync NT GEMM -- work-per-barrier maximized (R11 intent, staging
// map FIXED: each 64-float row = 16 cp.16 chunks; 256 threads x 24 chunks
// cover all 384x16 chunks per stage).
// C[M,Nt] = A[M,K] @ W[Nt,K]^T + bias[Nt].  Inputs pre-rounded tf32.
// Block 256(M) x 128(N), BK=64, 256 threads = 8 warps (4m x 2n), 64x64 each
// -> 256 HMMA per warp per chunk between barriers. 2-stage ring (209KB,
// 1 CTA/SM), 16 chunks. Pitch 68 (==4 mod 32, ldmatrix-safe).
// Staging rows: A 0..255, B 256..383.
// ===========================================================================
#define GP 68
#define GSTG (384 * GP)                  // floats per stage
#define GEMM_SMEM (2 * GSTG * 4)         // 208896 B

__global__ __launch_bounds__(256, 1)
void gemm_mma_tf32(const float* __restrict__ A, const float* __restrict__ W,
                   const float* __restrict__ bias, float* __restrict__ Cout,
                   int M, int Nt, int K, int round_out)
{
    extern __shared__ float smf[];
    const uint32_t smb = smem_u32(smf);
    const int t      = threadIdx.x;
    const int lane   = t & 31;
    const int r      = lane >> 2;
    const int cq     = lane & 3;
    const int g      = lane >> 3;
    const int j      = lane & 7;
    const int wid    = t >> 5;
    const int warp_m = wid & 3;     // 4 warps over M (64 rows each)
    const int warp_n = wid >> 2;    // 2 warps over N (64 cols each)
    const int m0 = blockIdx.y << 8;
    const int n0 = blockIdx.x << 7;

    // ldmatrix per-lane base offsets (bytes, within a stage)
    const uint32_t a_lane = (uint32_t)(((warp_m * 64 + (g & 1) * 8 + j) * GP
                                        + (g >> 1) * 4) * 4);
    const uint32_t b_lane = (uint32_t)(((256 + warp_n * 64 + (g >> 1) * 8 + j) * GP
                                        + (g & 1) * 4) * 4);

    // staging map: 384 rows x 16 chunks (16B) = 6144 cp.16; 24 per thread.
    const int grow = t >> 4;              // 0..15 (x24 via p)
    const int gc4  = (t & 15) << 2;       // 0,4,...,60 (float offset)

#define ISSUE_CHUNK(cidx, s)                                                   \
    {                                                                          \
        const float* Ap = A + (size_t)m0 * K + (cidx) * 64;                    \
        const float* Wp = W + (size_t)n0 * K + (cidx) * 64;                    \
        const uint32_t sb = smb + (uint32_t)((s) * GSTG * 4);                  \
        _Pragma("unroll")                                                      \
        for (int p = 0; p < 24; p++) {                                         \
            int row = grow + p * 16;                                           \
            const float* src = (row < 256)                                     \
                ? Ap + (size_t)row * K + gc4                                   \
                : Wp + (size_t)(row - 256) * K + gc4;                          \
            CP16(sb + (uint32_t)((row * GP + gc4) * 4), src);                  \
        }                                                                      \
        CP_COMMIT();                                                           \
    }

    float acc[4][8][4];
#pragma unroll
    for (int i = 0; i < 4; i++)
#pragma unroll
        for (int jj = 0; jj < 8; jj++)
#pragma unroll
            for (int e = 0; e < 4; e++) acc[i][jj][e] = 0.f;

    const int nch = K / 64;
    ISSUE_CHUNK(0, 0);
    ISSUE_CHUNK(1, 1);

    for (int c = 0; c < nch; c++) {
        const int s = c & 1;
        if (c + 1 < nch) CP_WAIT1(); else CP_WAIT0();
        __syncthreads();

        const uint32_t sbase = smb + (uint32_t)(s * GSTG * 4);
#pragma unroll
        for (int ks = 0; ks < 8; ks++) {
            uint32_t afr[4][4], bfr[8][2];
#pragma unroll
            for (int mt = 0; mt < 4; mt++)
                ldsm_x4(sbase + a_lane + (uint32_t)((mt * 16 * GP + ks * 8) * 4),
                        afr[mt]);
#pragma unroll
            for (int p = 0; p < 4; p++) {
                uint32_t q[4];
                ldsm_x4(sbase + b_lane + (uint32_t)((p * 16 * GP + ks * 8) * 4), q);
                bfr[2 * p][0] = q[0]; bfr[2 * p][1] = q[1];
                bfr[2 * p + 1][0] = q[2]; bfr[2 * p + 1][1] = q[3];
            }
#pragma unroll
            for (int mt = 0; mt < 4; mt++)
#pragma unroll
                for (int nt = 0; nt < 8; nt++)
                    mma_tf32(acc[mt][nt], afr[mt], bfr[nt]);
        }

        // 2-stage ring: chunk c+2 overwrites the stage just read -> all warps
        // must be done with it before issue.
        if (c + 2 < nch) {
            __syncthreads();
            ISSUE_CHUNK(c + 2, s);
        }
    }

    // Epilogue: bias, optional tf32 rounding, direct stores
    const int c2 = cq << 1;
#pragma unroll
    for (int nt = 0; nt < 8; nt++) {
        const int gn = n0 + warp_n * 64 + nt * 8 + c2;
        const float b0 = bias[gn], b1 = bias[gn + 1];
#pragma unroll
        for (int mt = 0; mt < 4; mt++) {
            const int gm = m0 + warp_m * 64 + mt * 16 + r;
            float2 v0, v1;
            v0.x = acc[mt][nt][0] + b0; v0.y = acc[mt][nt][1] + b1;
            v1.x = acc[mt][nt][2] + b0; v1.y = acc[mt][nt][3] + b1;
            if (round_out) {
                v0.x = __uint_as_float(f2tf32(v0.x));
                v0.y = __uint_as_float(f2tf32(v0.y));
                v1.x = __uint_as_float(f2tf32(v1.x));
                v1.y = __uint_as_float(f2tf32(v1.y));
            }
            *(float2*)&Cout[(size_t)gm * Nt + gn]       = v0;
            *(float2*)&Cout[(size_t)(gm + 8) * Nt + gn] = v1;
        }
    }
#undef ISSUE_CHUNK
}

// ===========================================================================
// Flash attention (R9 structure; trailing barrier removed -- verified safe:
// all reads of tile kt-1 precede each thread's arrival at the top barrier of
// iteration kt, and distance-2 issue writes stage (kt+2)%3 != kt%3).
// tf32 mma.sync, 32-query warps, cp.async K/V ring, ldmatrix Q/K frags,
// k-perm PV register reuse. AQ=256, 256 threads = 8 warps x 32 rows.
// ===========================================================================
#define AQ      256
#define AP      68
#define KSTG    (2 * 64 * AP)                 // K+V one stage (floats)
#define OFF_KV  (AQ * AP)
#define ATTN_SMEM ((AQ * AP + 3 * KSTG) * 4)  // 174080 B

__global__ __launch_bounds__(256, 1)
void attn_mma(const float* __restrict__ qkv, float* __restrict__ out)
{
    extern __shared__ float sm[];
    const uint32_t smb = smem_u32(sm);
    const int t    = threadIdx.x;
    const int lane = t & 31;
    const int wid  = t >> 5;
    const int r    = lane >> 2;
    const int cq   = lane & 3;
    const int g    = lane >> 3;
    const int j    = lane & 7;
    const int q0   = blockIdx.x * AQ;
    const int b    = blockIdx.y >> 4;
    const int h    = blockIdx.y & 15;
    const int rs   = 3 * C_DIM;

    const float* qb = qkv + ((size_t)(b * NSEQ + q0) * 3) * C_DIM + h * HDIM;
    const float* kb = qkv + ((size_t)(b * NSEQ) * 3 + 1) * C_DIM + h * HDIM;
    const float* vb = qkv + ((size_t)(b * NSEQ) * 3 + 2) * C_DIM + h * HDIM;

    const int wrow = wid * 32;   // warp's query-row base (32 rows)

    const uint32_t q_lane = (uint32_t)(((wrow + (g & 1) * 8 + j) * AP
                                        + (g >> 1) * 4) * 4);
    const uint32_t k_lane = (uint32_t)((((g >> 1) * 8 + j) * AP
                                        + (g & 1) * 4) * 4);

    const int srow = t >> 4;              // 0..15 (x4 via p)
    const int sd4  = (t & 15) << 2;

    // ---- Q via cp.async (group 0) ----
#pragma unroll
    for (int p = 0; p < 16; p++) {
        int row = srow + p * 16;
        CP16(smb + (uint32_t)((row * AP + sd4) * 4), qb + (size_t)row * rs + sd4);
    }
    CP_COMMIT();

#define ISSUE_KV(kt, s)                                                        \
    {                                                                          \
        const float* kn = kb + (size_t)((kt) * 64) * rs;                       \
        const float* vn = vb + (size_t)((kt) * 64) * rs;                       \
        const uint32_t sb = smb + (uint32_t)((OFF_KV + (s) * KSTG) * 4);       \
        _Pragma("unroll")                                                      \
        for (int p = 0; p < 4; p++) {                                          \
            int row = srow + p * 16;                                           \
            CP16(sb + (uint32_t)((row * AP + sd4) * 4),                        \
                 kn + (size_t)row * rs + sd4);                                 \
            CP16(sb + (uint32_t)((64 * AP + row * AP + sd4) * 4),              \
                 vn + (size_t)row * rs + sd4);                                 \
        }                                                                      \
        CP_COMMIT();                                                           \
    }

    ISSUE_KV(0, 0);
    ISSUE_KV(1, 1);

    float o_[2][8][4];
#pragma unroll
    for (int mt = 0; mt < 2; mt++)
#pragma unroll
        for (int nt = 0; nt < 8; nt++)
#pragma unroll
            for (int e = 0; e < 4; e++) o_[mt][nt][e] = 0.f;
    float m_r[2][2], l_r[2][2];
#pragma unroll
    for (int mt = 0; mt < 2; mt++) {
        m_r[mt][0] = -1e30f; m_r[mt][1] = -1e30f;
        l_r[mt][0] = 0.f;    l_r[mt][1] = 0.f;
    }

    const int NT = NSEQ / 64;
    int stage = 0;
    for (int kt = 0; kt < NT; kt++) {
        if (kt + 1 < NT) CP_WAIT1(); else CP_WAIT0();
        __syncthreads();
        if (kt + 2 < NT) {
            int ns = stage + 2; if (ns >= 3) ns -= 3;
            ISSUE_KV(kt + 2, ns);
        }

        const uint32_t kbase = smb + (uint32_t)((OFF_KV + stage * KSTG) * 4);
        const float*   Vst   = &sm[OFF_KV + stage * KSTG + 64 * AP];

        // ---- S = Q @ K^T (warp: 32 rows x 64 cols) ----
        float s_[2][8][4];
#pragma unroll
        for (int mt = 0; mt < 2; mt++)
#pragma unroll
            for (int nt = 0; nt < 8; nt++)
#pragma unroll
                for (int e = 0; e < 4; e++) s_[mt][nt][e] = 0.f;

#pragma unroll
        for (int ks = 0; ks < 8; ks++) {
            uint32_t aq[2][4];
            ldsm_x4(smb + q_lane + (uint32_t)(ks * 32), aq[0]);
            ldsm_x4(smb + q_lane + (uint32_t)(16 * AP * 4 + ks * 32), aq[1]);
#pragma unroll
            for (int p = 0; p < 4; p++) {
                uint32_t qv[4];
                ldsm_x4(kbase + k_lane + (uint32_t)((p * 16 * AP) * 4 + ks * 32), qv);
                uint32_t b0[2] = {qv[0], qv[1]};
                uint32_t b1[2] = {qv[2], qv[3]};
                mma_tf32(s_[0][2 * p],     aq[0], b0);
                mma_tf32(s_[0][2 * p + 1], aq[0], b1);
                mma_tf32(s_[1][2 * p],     aq[1], b0);
                mma_tf32(s_[1][2 * p + 1], aq[1], b1);
            }
        }

        // ---- online softmax ----
#pragma unroll
        for (int mt = 0; mt < 2; mt++) {
            float ml0 = -1e30f, ml1 = -1e30f;
#pragma unroll
            for (int nt = 0; nt < 8; nt++) {
                s_[mt][nt][0] *= ATT_SCALE; s_[mt][nt][1] *= ATT_SCALE;
                s_[mt][nt][2] *= ATT_SCALE; s_[mt][nt][3] *= ATT_SCALE;
                ml0 = fmaxf(ml0, fmaxf(s_[mt][nt][0], s_[mt][nt][1]));
                ml1 = fmaxf(ml1, fmaxf(s_[mt][nt][2], s_[mt][nt][3]));
            }
            ml0 = fmaxf(ml0, __shfl_xor_sync(0xffffffffu, ml0, 1));
            ml0 = fmaxf(ml0, __shfl_xor_sync(0xffffffffu, ml0, 2));
            ml1 = fmaxf(ml1, __shfl_xor_sync(0xffffffffu, ml1, 1));
            ml1 = fmaxf(ml1, __shfl_xor_sync(0xffffffffu, ml1, 2));

            float mn0 = fmaxf(m_r[mt][0], ml0), mn1 = fmaxf(m_r[mt][1], ml1);
            float cr0 = __expf(m_r[mt][0] - mn0), cr1 = __expf(m_r[mt][1] - mn1);
            m_r[mt][0] = mn0; m_r[mt][1] = mn1;

            float rs0 = 0.f, rs1 = 0.f;
#pragma unroll
            for (int nt = 0; nt < 8; nt++) {
                s_[mt][nt][0] = __expf(s_[mt][nt][0] - mn0);
                s_[mt][nt][1] = __expf(s_[mt][nt][1] - mn0);
                s_[mt][nt][2] = __expf(s_[mt][nt][2] - mn1);
                s_[mt][nt][3] = __expf(s_[mt][nt][3] - mn1);
                rs0 += s_[mt][nt][0] + s_[mt][nt][1];
                rs1 += s_[mt][nt][2] + s_[mt][nt][3];
            }
            rs0 += __shfl_xor_sync(0xffffffffu, rs0, 1);
            rs0 += __shfl_xor_sync(0xffffffffu, rs0, 2);
            rs1 += __shfl_xor_sync(0xffffffffu, rs1, 1);
            rs1 += __shfl_xor_sync(0xffffffffu, rs1, 2);
            l_r[mt][0] = l_r[mt][0] * cr0 + rs0;
            l_r[mt][1] = l_r[mt][1] * cr1 + rs1;

#pragma unroll
            for (int nt = 0; nt < 8; nt++) {
                o_[mt][nt][0] *= cr0; o_[mt][nt][1] *= cr0;
                o_[mt][nt][2] *= cr1; o_[mt][nt][3] *= cr1;
            }
        }

        // ---- O += P @ V : P straight from s_ registers (k-perm) ----
#pragma unroll
        for (int ks = 0; ks < 8; ks++) {
            uint32_t a0[4], a1[4];
            a0[0] = f2tf32(s_[0][ks][0]); a0[1] = f2tf32(s_[0][ks][2]);
            a0[2] = f2tf32(s_[0][ks][1]); a0[3] = f2tf32(s_[0][ks][3]);
            a1[0] = f2tf32(s_[1][ks][0]); a1[1] = f2tf32(s_[1][ks][2]);
            a1[2] = f2tf32(s_[1][ks][1]); a1[3] = f2tf32(s_[1][ks][3]);
            const float* Vb = Vst + (ks * 8 + 2 * cq) * AP + r;
#pragma unroll
            for (int nt = 0; nt < 8; nt++) {
                uint32_t bf[2];
                bf[0] = __float_as_uint(Vb[nt * 8]);
                bf[1] = __float_as_uint(Vb[nt * 8 + AP]);
                mma_tf32(o_[0][nt], a0, bf);
                mma_tf32(o_[1][nt], a1, bf);
            }
        }

        if (++stage == 3) stage = 0;
        // trailing barrier removed (top-of-loop barrier suffices; ring dist 2)
    }

    // ---- epilogue: normalize, round to tf32 (feeds proj gemm), store ----
#pragma unroll
    for (int mt = 0; mt < 2; mt++) {
        const float i0 = 1.f / l_r[mt][0], i1 = 1.f / l_r[mt][1];
        const int row0 = b * NSEQ + q0 + wrow + mt * 16 + r;
#pragma unroll
        for (int nt = 0; nt < 8; nt++) {
            const int col = h * HDIM + nt * 8 + 2 * cq;
            float2 v0, v1;
            v0.x = __uint_as_float(f2tf32(o_[mt][nt][0] * i0));
            v0.y = __uint_as_float(f2tf32(o_[mt][nt][1] * i0));
            v1.x = __uint_as_float(f2tf32(o_[mt][nt][2] * i1));
            v1.y = __uint_as_float(f2tf32(o_[mt][nt][3] * i1));
            *(float2*)&out[(size_t)row0 * C_DIM + col]       = v0;
            *(float2*)&out[(size_t)(row0 + 8) * C_DIM + col] = v1;
        }
    }
#undef ISSUE_KV
}

// ---------------------------------------------------------------------------
extern "C" void kernel_launch(void* const* d_in, const int* in_sizes, int n_in,
                              void* d_out, int out_size)
{
    const float* x      = (const float*)d_in[0];
    const float* w_qkv  = (const float*)d_in[1];
    const float* b_qkv  = (const float*)d_in[2];
    const float* w_proj = (const float*)d_in[3];
    const float* b_proj = (const float*)d_in[4];
    float* out = (float*)d_out;

    float *qkv_s, *att_s, *xtf, *wqtf, *wptf;
    cudaGetSymbolAddress((void**)&qkv_s, g_qkv);
    cudaGetSymbolAddress((void**)&att_s, g_att);
    cudaGetSymbolAddress((void**)&xtf,   g_xtf);
    cudaGetSymbolAddress((void**)&wqtf,  g_wqkv_tf);
    cudaGetSymbolAddress((void**)&wptf,  g_wproj_tf);

    cudaFuncSetAttribute(gemm_mma_tf32, cudaFuncAttributeMaxDynamicSharedMemorySize, GEMM_SMEM);
    cudaFuncSetAttribute(attn_mma, cudaFuncAttributeMaxDynamicSharedMemorySize, ATTN_SMEM);

    // 0) Pre-round inputs to tf32 (single merged launch)
    cvt3_tf32<<<1184, 256>>>(x, xtf, ROWS * C_DIM / 4,
                             w_qkv, wqtf, 3 * C_DIM * C_DIM / 4,
                             w_proj, wptf, C_DIM * C_DIM / 4);

    // 1) QKV projection -> tf32-rounded [4096,3072]
    dim3 g1(3 * C_DIM / 128, ROWS / 256);
    gemm_mma_tf32<<<g1, 256, GEMM_SMEM>>>(xtf, wqtf, b_qkv, qkv_s,
                                          ROWS, 3 * C_DIM, C_DIM, 1);

    // 2) Fused attention -> tf32-rounded [4096,1024]
    dim3 g2(NSEQ / AQ, BATCH * NHEADS);
    attn_mma<<<g2, 256, ATTN_SMEM>>>(qkv_s, att_s);

    // 3) Output projection -> fp32 out
    dim3 g3(C_DIM / 128, ROWS / 256);
    gemm_mma_tf32<<<g3, 256, GEMM_SMEM>>>(att_s, wptf, b_proj, out,
                                          ROWS, C_DIM, C_DIM, 0);
}

// round 13
// speedup vs baseline: 1.5640x; 1.5274x over previous
#include <cuda_runtime.h>
#include <cuda_fp16.h>
#include <cstdint>

#define C_DIM   1024
#define NSEQ    2048
#define NHEADS  16
#define HDIM    64
#define BATCH   2
#define ROWS    (BATCH * NSEQ)       // 4096
#define ATT_SCALE 0.125f             // 1/sqrt(64)

// Scratch (no allocations allowed in kernel_launch) -- all fp16 now
__device__ __half g_qkvh[ROWS * 3 * C_DIM];       // [4096, 3072]
__device__ __half g_atth[ROWS * C_DIM];           // [4096, 1024]
__device__ __half g_xh[ROWS * C_DIM];             // x
__device__ __half g_wqkvh[3 * C_DIM * C_DIM];     // w_qkv
__device__ __half g_wprojh[C_DIM * C_DIM];        // w_proj

// ===========================================================================
// helpers (arch-independent PTX, sm_80+)
// ===========================================================================
__device__ __forceinline__ uint32_t smem_u32(const void* p) {
    uint32_t a;
    asm("{ .reg .u64 t; cvta.to.shared.u64 t, %1; cvt.u32.u64 %0, t; }"
        : "=r"(a) : "l"(p));
    return a;
}
__device__ __forceinline__ void ldsm_x4(uint32_t addr, uint32_t* d) {
    asm volatile("ldmatrix.sync.aligned.m8n8.x4.shared.b16 {%0,%1,%2,%3}, [%4];"
                 : "=r"(d[0]), "=r"(d[1]), "=r"(d[2]), "=r"(d[3]) : "r"(addr));
}
__device__ __forceinline__ void ldsm_x4t(uint32_t addr, uint32_t* d) {
    asm volatile("ldmatrix.sync.aligned.m8n8.x4.trans.shared.b16 {%0,%1,%2,%3}, [%4];"
                 : "=r"(d[0]), "=r"(d[1]), "=r"(d[2]), "=r"(d[3]) : "r"(addr));
}
// D += A @ B, m16n8k16 f16 inputs, f32 accumulate.
__device__ __forceinline__ void mma_f16(float* d, const uint32_t* a, const uint32_t* b) {
    asm volatile(
        "mma.sync.aligned.m16n8k16.row.col.f32.f16.f16.f32 "
        "{%0,%1,%2,%3}, {%4,%5,%6,%7}, {%8,%9}, {%0,%1,%2,%3};"
        : "+f"(d[0]), "+f"(d[1]), "+f"(d[2]), "+f"(d[3])
        : "r"(a[0]), "r"(a[1]), "r"(a[2]), "r"(a[3]), "r"(b[0]), "r"(b[1]));
}
__device__ __forceinline__ uint32_t pack_h2(float lo, float hi) {
    __half2 h = __floats2half2_rn(lo, hi);
    return *reinterpret_cast<uint32_t*>(&h);
}
#define CP16(dst, src) \
    asm volatile("cp.async.cg.shared.global [%0], [%1], 16;" \
                 :: "r"(dst), "l"(src) : "memory")
#define CP_COMMIT() asm volatile("cp.async.commit_group;" ::: "memory")
#define CP_WAIT1()  asm volatile("cp.async.wait_group 1;" ::: "memory")
#define CP_WAIT0()  asm volatile("cp.async.wait_group 0;" ::: "memory")

// ===========================================================================
// Merged pre-pass: fp32 -> fp16 for x, w_qkv, w_proj.
// ===========================================================================
__global__ void cvt3_f16(const float* a, __half* oa, int na4,
                         const float* b, __half* ob, int nb4,
                         const float* c, __half* oc, int nc4)
{
    int i = blockIdx.x * blockDim.x + threadIdx.x;
    int stride = gridDim.x * blockDim.x;
    int tot = na4 + nb4 + nc4;
    for (; i < tot; i += stride) {
        const float4* src;
        uint2* dst;
        int k = i;
        if (k < na4) { src = (const float4*)a + k; dst = (uint2*)oa + k; }
        else if ((k -= na4) < nb4) { src = (const float4*)b + k; dst = (uint2*)ob + k; }
        else { k -= nb4; src = (const float4*)c + k; dst = (uint2*)oc + k; }
        float4 v = *src;
        uint2 u;
        u.x = pack_h2(v.x, v.y);
        u.y = pack_h2(v.z, v.w);
        *dst = u;
    }
}

// ===========================================================================
// fp16 mma.sync NT GEMM (R9 shape): C[M,Nt] = A[M,K] @ W[Nt,K]^T + bias[Nt]
// A, W fp16; bias fp32; output half (half_out=1) or float (0).
// 128x128 tile, BK=32, 256 threads (8 warps, 64x32 each), 2 CTAs/SM.
// Pitch 40 halves (80B = 5*16B -> ldmatrix rows conflict-free & 16B-aligned).
// Per chunk: 2 k16-steps x (6 ldsm + 16 mma). 3-stage cp.async ring.
// ===========================================================================
#define GPH 40
#define GSTGH (256 * GPH)                // halves per stage (A 128 + B 128 rows)
#define GEMM_SMEM (3 * GSTGH * 2)        // 61440 B

__global__ __launch_bounds__(256, 2)
void gemm_mma_f16(const __half* __restrict__ A, const __half* __restrict__ W,
                  const float* __restrict__ bias, void* __restrict__ Cout,
                  int M, int Nt, int K, int half_out)
{
    extern __shared__ __half smh[];
    const uint32_t smb = smem_u32(smh);
    const int t      = threadIdx.x;
    const int lane   = t & 31;
    const int r      = lane >> 2;
    const int cq     = lane & 3;
    const int g      = lane >> 3;
    const int j      = lane & 7;
    const int wid    = t >> 5;
    const int warp_m = wid & 1;     // 2 warps over M (64 rows each)
    const int warp_n = wid >> 1;    // 4 warps over N (32 cols each)
    const int m0 = blockIdx.y << 7;
    const int n0 = blockIdx.x << 7;

    // ldmatrix per-lane base offsets (bytes, within a stage)
    const uint32_t a_lane = (uint32_t)(((warp_m * 64 + (g & 1) * 8 + j) * GPH
                                        + (g >> 1) * 8) * 2);
    const uint32_t b_lane = (uint32_t)(((128 + warp_n * 32 + (g & 1) * 8 + j) * GPH
                                        + (g >> 1) * 8) * 2);

    // staging: 256 rows x 32 halves = 4 x 16B chunks/row; 1024 cp, 4/thread
    const int grow = t >> 2;              // 0..63 (x4 via p)
    const int gc8  = (t & 3) << 3;        // 0,8,16,24 (half offset)

#define ISSUE_CHUNK(cidx, s)                                                   \
    {                                                                          \
        const __half* Ap = A + (size_t)m0 * K + (cidx) * 32;                   \
        const __half* Wp = W + (size_t)n0 * K + (cidx) * 32;                   \
        const uint32_t sb = smb + (uint32_t)((s) * GSTGH * 2);                 \
        _Pragma("unroll")                                                      \
        for (int p = 0; p < 4; p++) {                                          \
            int row = grow + p * 64;                                           \
            const __half* src = (row < 128)                                    \
                ? Ap + (size_t)row * K + gc8                                   \
                : Wp + (size_t)(row - 128) * K + gc8;                          \
            CP16(sb + (uint32_t)((row * GPH + gc8) * 2), src);                 \
        }                                                                      \
        CP_COMMIT();                                                           \
    }

    float acc[4][4][4];
#pragma unroll
    for (int i = 0; i < 4; i++)
#pragma unroll
        for (int jj = 0; jj < 4; jj++)
#pragma unroll
            for (int e = 0; e < 4; e++) acc[i][jj][e] = 0.f;

    const int nch = K / 32;
    ISSUE_CHUNK(0, 0);
    ISSUE_CHUNK(1, 1);

    int stage = 0;
    for (int c = 0; c < nch; c++) {
        if (c + 1 < nch) CP_WAIT1(); else CP_WAIT0();
        __syncthreads();
        if (c + 2 < nch) {
            int ns = stage + 2; if (ns >= 3) ns -= 3;
            ISSUE_CHUNK(c + 2, ns);
        }

        const uint32_t sbase = smb + (uint32_t)(stage * GSTGH * 2);
#pragma unroll
        for (int ks = 0; ks < 2; ks++) {
            uint32_t afr[4][4], bfr[4][2];
#pragma unroll
            for (int mt = 0; mt < 4; mt++)
                ldsm_x4(sbase + a_lane + (uint32_t)((mt * 16 * GPH + ks * 16) * 2),
                        afr[mt]);
#pragma unroll
            for (int p = 0; p < 2; p++) {
                uint32_t q[4];
                ldsm_x4(sbase + b_lane + (uint32_t)((p * 16 * GPH + ks * 16) * 2), q);
                bfr[2 * p][0] = q[0]; bfr[2 * p][1] = q[2];
                bfr[2 * p + 1][0] = q[1]; bfr[2 * p + 1][1] = q[3];
            }
#pragma unroll
            for (int mt = 0; mt < 4; mt++)
#pragma unroll
                for (int nt = 0; nt < 4; nt++)
                    mma_f16(acc[mt][nt], afr[mt], bfr[nt]);
        }
        if (++stage == 3) stage = 0;
        __syncthreads();
    }

    // Epilogue: bias, store half2 (intermediate) or float2 (final)
    const int c2 = cq << 1;
#pragma unroll
    for (int nt = 0; nt < 4; nt++) {
        const int gn = n0 + warp_n * 32 + nt * 8 + c2;
        const float b0 = bias[gn], b1 = bias[gn + 1];
#pragma unroll
        for (int mt = 0; mt < 4; mt++) {
            const int gm = m0 + warp_m * 64 + mt * 16 + r;
            float x0 = acc[mt][nt][0] + b0, y0 = acc[mt][nt][1] + b1;
            float x1 = acc[mt][nt][2] + b0, y1 = acc[mt][nt][3] + b1;
            if (half_out) {
                __half* Ch = (__half*)Cout;
                *(uint32_t*)&Ch[(size_t)gm * Nt + gn]       = pack_h2(x0, y0);
                *(uint32_t*)&Ch[(size_t)(gm + 8) * Nt + gn] = pack_h2(x1, y1);
            } else {
                float* Cf = (float*)Cout;
                *(float2*)&Cf[(size_t)gm * Nt + gn]       = make_float2(x0, y0);
                *(float2*)&Cf[(size_t)(gm + 8) * Nt + gn] = make_float2(x1, y1);
            }
        }
    }
#undef ISSUE_CHUNK
}

// ===========================================================================
// Flash attention, fp16 (R9 structure): mma.m16n8k16, 32-query warps,
// cp.async 3-stage K/V ring, ldmatrix Q/K frags, ldmatrix.trans V frags,
// P packed straight from fp32 S registers (natural f16 packing, no k-perm).
// AQ=256, 256 threads = 8 warps x 32 rows. Pitch 72 halves (144B = 9*16B).
// ===========================================================================
#define AQ      256
#define APH     72
#define KSTGH   (2 * 64 * APH)                // K+V one stage (halves)
#define OFF_KVH (AQ * APH)
#define ATTN_SMEM ((OFF_KVH + 3 * KSTGH) * 2) // 92160 B

__global__ __launch_bounds__(256, 1)
void attn_mma(const __half* __restrict__ qkv, __half* __restrict__ out)
{
    extern __shared__ __half smh[];
    const uint32_t smb = smem_u32(smh);
    const int t    = threadIdx.x;
    const int lane = t & 31;
    const int wid  = t >> 5;
    const int r    = lane >> 2;
    const int cq   = lane & 3;
    const int g    = lane >> 3;
    const int j    = lane & 7;
    const int q0   = blockIdx.x * AQ;
    const int b    = blockIdx.y >> 4;
    const int h    = blockIdx.y & 15;
    const int rs   = 3 * C_DIM;

    const __half* qb = qkv + ((size_t)(b * NSEQ + q0) * 3) * C_DIM + h * HDIM;
    const __half* kb = qkv + ((size_t)(b * NSEQ) * 3 + 1) * C_DIM + h * HDIM;
    const __half* vb = qkv + ((size_t)(b * NSEQ) * 3 + 2) * C_DIM + h * HDIM;

    const int wrow = wid * 32;   // warp's query-row base (32 rows)

    const uint32_t q_lane = (uint32_t)(((wrow + (g & 1) * 8 + j) * APH
                                        + (g >> 1) * 8) * 2);
    const uint32_t k_lane = (uint32_t)((((g & 1) * 8 + j) * APH
                                        + (g >> 1) * 8) * 2);

    // staging: rows of 64 halves = 8 x 16B chunks
    const int srow = t >> 3;              // 0..31
    const int sc8  = (t & 7) << 3;        // half offset 0..56

    // ---- Q via cp.async (group 0): 256 rows -> 8 per thread ----
#pragma unroll
    for (int p = 0; p < 8; p++) {
        int row = srow + p * 32;
        CP16(smb + (uint32_t)((row * APH + sc8) * 2), qb + (size_t)row * rs + sc8);
    }
    CP_COMMIT();

#define ISSUE_KV(kt, s)                                                        \
    {                                                                          \
        const __half* kn = kb + (size_t)((kt) * 64) * rs;                      \
        const __half* vn = vb + (size_t)((kt) * 64) * rs;                      \
        const uint32_t sb = smb + (uint32_t)((OFF_KVH + (s) * KSTGH) * 2);     \
        _Pragma("unroll")                                                      \
        for (int p = 0; p < 2; p++) {                                          \
            int row = srow + p * 32;                                           \
            CP16(sb + (uint32_t)((row * APH + sc8) * 2),                       \
                 kn + (size_t)row * rs + sc8);                                 \
            CP16(sb + (uint32_t)((64 * APH + row * APH + sc8) * 2),            \
                 vn + (size_t)row * rs + sc8);                                 \
        }                                                                      \
        CP_COMMIT();                                                           \
    }

    ISSUE_KV(0, 0);
    ISSUE_KV(1, 1);

    float o_[2][8][4];
#pragma unroll
    for (int mt = 0; mt < 2; mt++)
#pragma unroll
        for (int nt = 0; nt < 8; nt++)
#pragma unroll
            for (int e = 0; e < 4; e++) o_[mt][nt][e] = 0.f;
    float m_r[2][2], l_r[2][2];
#pragma unroll
    for (int mt = 0; mt < 2; mt++) {
        m_r[mt][0] = -1e30f; m_r[mt][1] = -1e30f;
        l_r[mt][0] = 0.f;    l_r[mt][1] = 0.f;
    }

    const int NT = NSEQ / 64;
    int stage = 0;
    for (int kt = 0; kt < NT; kt++) {
        if (kt + 1 < NT) CP_WAIT1(); else CP_WAIT0();
        __syncthreads();
        if (kt + 2 < NT) {
            int ns = stage + 2; if (ns >= 3) ns -= 3;
            ISSUE_KV(kt + 2, ns);
        }

        const uint32_t kbase = smb + (uint32_t)((OFF_KVH + stage * KSTGH) * 2);
        const uint32_t vbase = kbase + (uint32_t)(64 * APH * 2);

        // ---- S = Q @ K^T (warp: 32 rows x 64 cols), 4 k16-steps over d ----
        float s_[2][8][4];
#pragma unroll
        for (int mt = 0; mt < 2; mt++)
#pragma unroll
            for (int nt = 0; nt < 8; nt++)
#pragma unroll
                for (int e = 0; e < 4; e++) s_[mt][nt][e] = 0.f;

#pragma unroll
        for (int ks = 0; ks < 4; ks++) {
            uint32_t aq[2][4];
            ldsm_x4(smb + q_lane + (uint32_t)(ks * 32), aq[0]);
            ldsm_x4(smb + q_lane + (uint32_t)(16 * APH * 2 + ks * 32), aq[1]);
#pragma unroll
            for (int p = 0; p < 4; p++) {
                uint32_t qv[4];
                ldsm_x4(kbase + k_lane + (uint32_t)((p * 16 * APH) * 2 + ks * 32), qv);
                uint32_t b0[2] = {qv[0], qv[2]};
                uint32_t b1[2] = {qv[1], qv[3]};
                mma_f16(s_[0][2 * p],     aq[0], b0);
                mma_f16(s_[0][2 * p + 1], aq[0], b1);
                mma_f16(s_[1][2 * p],     aq[1], b0);
                mma_f16(s_[1][2 * p + 1], aq[1], b1);
            }
        }

        // ---- online softmax (per mt: rows r and r+8; reduce over c-quad) ----
#pragma unroll
        for (int mt = 0; mt < 2; mt++) {
            float ml0 = -1e30f, ml1 = -1e30f;
#pragma unroll
            for (int nt = 0; nt < 8; nt++) {
                s_[mt][nt][0] *= ATT_SCALE; s_[mt][nt][1] *= ATT_SCALE;
                s_[mt][nt][2] *= ATT_SCALE; s_[mt][nt][3] *= ATT_SCALE;
                ml0 = fmaxf(ml0, fmaxf(s_[mt][nt][0], s_[mt][nt][1]));
                ml1 = fmaxf(ml1, fmaxf(s_[mt][nt][2], s_[mt][nt][3]));
            }
            ml0 = fmaxf(ml0, __shfl_xor_sync(0xffffffffu, ml0, 1));
            ml0 = fmaxf(ml0, __shfl_xor_sync(0xffffffffu, ml0, 2));
            ml1 = fmaxf(ml1, __shfl_xor_sync(0xffffffffu, ml1, 1));
            ml1 = fmaxf(ml1, __shfl_xor_sync(0xffffffffu, ml1, 2));

            float mn0 = fmaxf(m_r[mt][0], ml0), mn1 = fmaxf(m_r[mt][1], ml1);
            float cr0 = __expf(m_r[mt][0] - mn0), cr1 = __expf(m_r[mt][1] - mn1);
            m_r[mt][0] = mn0; m_r[mt][1] = mn1;

            float rs0 = 0.f, rs1 = 0.f;
#pragma unroll
            for (int nt = 0; nt < 8; nt++) {
                s_[mt][nt][0] = __expf(s_[mt][nt][0] - mn0);
                s_[mt][nt][1] = __expf(s_[mt][nt][1] - mn0);
                s_[mt][nt][2] = __expf(s_[mt][nt][2] - mn1);
                s_[mt][nt][3] = __expf(s_[mt][nt][3] - mn1);
                rs0 += s_[mt][nt][0] + s_[mt][nt][1];
                rs1 += s_[mt][nt][2] + s_[mt][nt][3];
            }
            rs0 += __shfl_xor_sync(0xffffffffu, rs0, 1);
            rs0 += __shfl_xor_sync(0xffffffffu, rs0, 2);
            rs1 += __shfl_xor_sync(0xffffffffu, rs1, 1);
            rs1 += __shfl_xor_sync(0xffffffffu, rs1, 2);
            l_r[mt][0] = l_r[mt][0] * cr0 + rs0;
            l_r[mt][1] = l_r[mt][1] * cr1 + rs1;

#pragma unroll
            for (int nt = 0; nt < 8; nt++) {
                o_[mt][nt][0] *= cr0; o_[mt][nt][1] *= cr0;
                o_[mt][nt][2] *= cr1; o_[mt][nt][3] *= cr1;
            }
        }

        // ---- O += P @ V, 4 k16-steps over keys.
        // f16 A-frag packing == S output pairing: a0 = {P[r][16ks+2cq],
        // P[r][16ks+2cq+1]} = pack(s_[2ks][0], s_[2ks][1]) etc. No smem for P.
        // V frags via ldmatrix.trans (V stored [key][d]).
#pragma unroll
        for (int ks = 0; ks < 4; ks++) {
            uint32_t a0[4], a1[4];
            a0[0] = pack_h2(s_[0][2 * ks][0],     s_[0][2 * ks][1]);
            a0[1] = pack_h2(s_[0][2 * ks][2],     s_[0][2 * ks][3]);
            a0[2] = pack_h2(s_[0][2 * ks + 1][0], s_[0][2 * ks + 1][1]);
            a0[3] = pack_h2(s_[0][2 * ks + 1][2], s_[0][2 * ks + 1][3]);
            a1[0] = pack_h2(s_[1][2 * ks][0],     s_[1][2 * ks][1]);
            a1[1] = pack_h2(s_[1][2 * ks][2],     s_[1][2 * ks][3]);
            a1[2] = pack_h2(s_[1][2 * ks + 1][0], s_[1][2 * ks + 1][1]);
            a1[3] = pack_h2(s_[1][2 * ks + 1][2], s_[1][2 * ks + 1][3]);
#pragma unroll
            for (int p = 0; p < 4; p++) {
                uint32_t qv[4];
                ldsm_x4t(vbase + k_lane
                         + (uint32_t)((ks * 16 * APH + p * 16) * 2), qv);
                uint32_t b0[2] = {qv[0], qv[1]};
                uint32_t b1[2] = {qv[2], qv[3]};
                mma_f16(o_[0][2 * p],     a0, b0);
                mma_f16(o_[0][2 * p + 1], a0, b1);
                mma_f16(o_[1][2 * p],     a1, b0);
                mma_f16(o_[1][2 * p + 1], a1, b1);
            }
        }

        if (++stage == 3) stage = 0;
        __syncthreads();
    }

    // ---- epilogue: normalize, store half2 to [4096,1024] ----
#pragma unroll
    for (int mt = 0; mt < 2; mt++) {
        const float i0 = 1.f / l_r[mt][0], i1 = 1.f / l_r[mt][1];
        const int row0 = b * NSEQ + q0 + wrow + mt * 16 + r;
#pragma unroll
        for (int nt = 0; nt < 8; nt++) {
            const int col = h * HDIM + nt * 8 + 2 * cq;
            *(uint32_t*)&out[(size_t)row0 * C_DIM + col] =
                pack_h2(o_[mt][nt][0] * i0, o_[mt][nt][1] * i0);
            *(uint32_t*)&out[(size_t)(row0 + 8) * C_DIM + col] =
                pack_h2(o_[mt][nt][2] * i1, o_[mt][nt][3] * i1);
        }
    }
#undef ISSUE_KV
}

// ---------------------------------------------------------------------------
extern "C" void kernel_launch(void* const* d_in, const int* in_sizes, int n_in,
                              void* d_out, int out_size)
{
    const float* x      = (const float*)d_in[0];
    const float* w_qkv  = (const float*)d_in[1];
    const float* b_qkv  = (const float*)d_in[2];
    const float* w_proj = (const float*)d_in[3];
    const float* b_proj = (const float*)d_in[4];
    float* out = (float*)d_out;

    __half *qkv_s, *att_s, *xh, *wqh, *wph;
    cudaGetSymbolAddress((void**)&qkv_s, g_qkvh);
    cudaGetSymbolAddress((void**)&att_s, g_atth);
    cudaGetSymbolAddress((void**)&xh,    g_xh);
    cudaGetSymbolAddress((void**)&wqh,   g_wqkvh);
    cudaGetSymbolAddress((void**)&wph,   g_wprojh);

    cudaFuncSetAttribute(gemm_mma_f16, cudaFuncAttributeMaxDynamicSharedMemorySize, GEMM_SMEM);
    cudaFuncSetAttribute(attn_mma, cudaFuncAttributeMaxDynamicSharedMemorySize, ATTN_SMEM);

    // 0) Pre-convert inputs to fp16 (single merged launch)
    cvt3_f16<<<1184, 256>>>(x, xh, ROWS * C_DIM / 4,
                            w_qkv, wqh, 3 * C_DIM * C_DIM / 4,
                            w_proj, wph, C_DIM * C_DIM / 4);

    // 1) QKV projection -> fp16 [4096,3072]
    dim3 g1(3 * C_DIM / 128, ROWS / 128);
    gemm_mma_f16<<<g1, 256, GEMM_SMEM>>>(xh, wqh, b_qkv, qkv_s,
                                         ROWS, 3 * C_DIM, C_DIM, 1);

    // 2) Fused attention -> fp16 [4096,1024]
    dim3 g2(NSEQ / AQ, BATCH * NHEADS);
    attn_mma<<<g2, 256, ATTN_SMEM>>>(qkv_s, att_s);

    // 3) Output projection -> fp32 out
    dim3 g3(C_DIM / 128, ROWS / 128);
    gemm_mma_f16<<<g3, 256, GEMM_SMEM>>>(att_s, wph, b_proj, out,
                                         ROWS, C_DIM, C_DIM, 0);
}

// round 14
// speedup vs baseline: 1.6897x; 1.0803x over previous
#include <cuda_runtime.h>
#include <cuda_fp16.h>
#include <cstdint>

#define C_DIM   1024
#define NSEQ    2048
#define NHEADS  16
#define HDIM    64
#define BATCH   2
#define ROWS    (BATCH * NSEQ)       // 4096
#define ATT_SCALE 0.125f             // 1/sqrt(64)

// Scratch (no allocations allowed in kernel_launch) -- all fp16
__device__ __half g_qkvh[ROWS * 3 * C_DIM];       // [4096, 3072]
__device__ __half g_atth[ROWS * C_DIM];           // [4096, 1024]
__device__ __half g_xh[ROWS * C_DIM];             // x
__device__ __half g_wqkvh[3 * C_DIM * C_DIM];     // w_qkv
__device__ __half g_wprojh[C_DIM * C_DIM];        // w_proj

// ===========================================================================
// helpers (arch-independent PTX, sm_80+)
// ===========================================================================
__device__ __forceinline__ uint32_t smem_u32(const void* p) {
    uint32_t a;
    asm("{ .reg .u64 t; cvta.to.shared.u64 t, %1; cvt.u32.u64 %0, t; }"
        : "=r"(a) : "l"(p));
    return a;
}
__device__ __forceinline__ void ldsm_x4(uint32_t addr, uint32_t* d) {
    asm volatile("ldmatrix.sync.aligned.m8n8.x4.shared.b16 {%0,%1,%2,%3}, [%4];"
                 : "=r"(d[0]), "=r"(d[1]), "=r"(d[2]), "=r"(d[3]) : "r"(addr));
}
__device__ __forceinline__ void ldsm_x4t(uint32_t addr, uint32_t* d) {
    asm volatile("ldmatrix.sync.aligned.m8n8.x4.trans.shared.b16 {%0,%1,%2,%3}, [%4];"
                 : "=r"(d[0]), "=r"(d[1]), "=r"(d[2]), "=r"(d[3]) : "r"(addr));
}
// D += A @ B, m16n8k16 f16 inputs, f32 accumulate.
__device__ __forceinline__ void mma_f16(float* d, const uint32_t* a, const uint32_t* b) {
    asm volatile(
        "mma.sync.aligned.m16n8k16.row.col.f32.f16.f16.f32 "
        "{%0,%1,%2,%3}, {%4,%5,%6,%7}, {%8,%9}, {%0,%1,%2,%3};"
        : "+f"(d[0]), "+f"(d[1]), "+f"(d[2]), "+f"(d[3])
        : "r"(a[0]), "r"(a[1]), "r"(a[2]), "r"(a[3]), "r"(b[0]), "r"(b[1]));
}
__device__ __forceinline__ uint32_t pack_h2(float lo, float hi) {
    __half2 h = __floats2half2_rn(lo, hi);
    return *reinterpret_cast<uint32_t*>(&h);
}
#define CP16(dst, src) \
    asm volatile("cp.async.cg.shared.global [%0], [%1], 16;" \
                 :: "r"(dst), "l"(src) : "memory")
#define CP_COMMIT() asm volatile("cp.async.commit_group;" ::: "memory")
#define CP_WAIT1()  asm volatile("cp.async.wait_group 1;" ::: "memory")
#define CP_WAIT0()  asm volatile("cp.async.wait_group 0;" ::: "memory")

// ===========================================================================
// Merged pre-pass: fp32 -> fp16 for x, w_qkv, w_proj.
// ===========================================================================
__global__ void cvt3_f16(const float* a, __half* oa, int na4,
                         const float* b, __half* ob, int nb4,
                         const float* c, __half* oc, int nc4)
{
    int i = blockIdx.x * blockDim.x + threadIdx.x;
    int stride = gridDim.x * blockDim.x;
    int tot = na4 + nb4 + nc4;
    for (; i < tot; i += stride) {
        const float4* src;
        uint2* dst;
        int k = i;
        if (k < na4) { src = (const float4*)a + k; dst = (uint2*)oa + k; }
        else if ((k -= na4) < nb4) { src = (const float4*)b + k; dst = (uint2*)ob + k; }
        else { k -= nb4; src = (const float4*)c + k; dst = (uint2*)oc + k; }
        float4 v = *src;
        uint2 u;
        u.x = pack_h2(v.x, v.y);
        u.y = pack_h2(v.z, v.w);
        *dst = u;
    }
}

// ===========================================================================
// fp16 mma.sync NT GEMM, BK=64: C[M,Nt] = A[M,K] @ W[Nt,K]^T + bias[Nt]
// 128x128 tile, 256 threads (8 warps, 64x32 each), 2 CTAs/SM.
// Per chunk: 4 k16-steps x (6 ldsm + 16 mma) = 64 HMMA/warp per barrier pair.
// 2-stage cp.async ring (73.7KB). Pitch 72 halves (144B; 144 mod 128 = 16 ->
// ldmatrix rows conflict-free, 16B-aligned). Staging loops split A/W (no
// per-cp conditional). Rows 0..127 = A, 128..255 = W.
// ===========================================================================
#define GPH 72
#define GSTGH (256 * GPH)                // halves per stage
#define GEMM_SMEM (2 * GSTGH * 2)        // 73728 B

__global__ __launch_bounds__(256, 2)
void gemm_mma_f16(const __half* __restrict__ A, const __half* __restrict__ W,
                  const float* __restrict__ bias, void* __restrict__ Cout,
                  int M, int Nt, int K, int half_out)
{
    extern __shared__ __half smh[];
    const uint32_t smb = smem_u32(smh);
    const int t      = threadIdx.x;
    const int lane   = t & 31;
    const int r      = lane >> 2;
    const int cq     = lane & 3;
    const int g      = lane >> 3;
    const int j      = lane & 7;
    const int wid    = t >> 5;
    const int warp_m = wid & 1;     // 2 warps over M (64 rows each)
    const int warp_n = wid >> 1;    // 4 warps over N (32 cols each)
    const int m0 = blockIdx.y << 7;
    const int n0 = blockIdx.x << 7;

    // ldmatrix per-lane base offsets (bytes, within a stage)
    const uint32_t a_lane = (uint32_t)(((warp_m * 64 + (g & 1) * 8 + j) * GPH
                                        + (g >> 1) * 8) * 2);
    const uint32_t b_lane = (uint32_t)(((128 + warp_n * 32 + (g & 1) * 8 + j) * GPH
                                        + (g >> 1) * 8) * 2);

    // staging: 256 rows x 64 halves = 8 x 16B chunks/row; 2048 cp, 8/thread
    const int srow = t >> 3;              // 0..31 (x4 via p)
    const int sc8  = (t & 7) << 3;        // half offset 0..56

#define ISSUE_CHUNK(cidx, s)                                                   \
    {                                                                          \
        const __half* Ap = A + (size_t)m0 * K + (cidx) * 64;                   \
        const __half* Wp = W + (size_t)n0 * K + (cidx) * 64;                   \
        const uint32_t sb = smb + (uint32_t)((s) * GSTGH * 2);                 \
        _Pragma("unroll")                                                      \
        for (int p = 0; p < 4; p++) {                                          \
            int row = srow + p * 32;                                           \
            CP16(sb + (uint32_t)((row * GPH + sc8) * 2),                       \
                 Ap + (size_t)row * K + sc8);                                  \
        }                                                                      \
        _Pragma("unroll")                                                      \
        for (int p = 0; p < 4; p++) {                                          \
            int row = srow + p * 32;                                           \
            CP16(sb + (uint32_t)(((128 + row) * GPH + sc8) * 2),               \
                 Wp + (size_t)row * K + sc8);                                  \
        }                                                                      \
        CP_COMMIT();                                                           \
    }

    float acc[4][4][4];
#pragma unroll
    for (int i = 0; i < 4; i++)
#pragma unroll
        for (int jj = 0; jj < 4; jj++)
#pragma unroll
            for (int e = 0; e < 4; e++) acc[i][jj][e] = 0.f;

    const int nch = K / 64;
    ISSUE_CHUNK(0, 0);
    ISSUE_CHUNK(1, 1);

    for (int c = 0; c < nch; c++) {
        const int s = c & 1;
        if (c + 1 < nch) CP_WAIT1(); else CP_WAIT0();
        __syncthreads();

        const uint32_t sbase = smb + (uint32_t)(s * GSTGH * 2);
#pragma unroll
        for (int ks = 0; ks < 4; ks++) {
            uint32_t afr[4][4], bfr[4][2];
#pragma unroll
            for (int mt = 0; mt < 4; mt++)
                ldsm_x4(sbase + a_lane + (uint32_t)((mt * 16 * GPH) * 2 + ks * 32),
                        afr[mt]);
#pragma unroll
            for (int p = 0; p < 2; p++) {
                uint32_t q[4];
                ldsm_x4(sbase + b_lane + (uint32_t)((p * 16 * GPH) * 2 + ks * 32), q);
                bfr[2 * p][0] = q[0]; bfr[2 * p][1] = q[2];
                bfr[2 * p + 1][0] = q[1]; bfr[2 * p + 1][1] = q[3];
            }
#pragma unroll
            for (int mt = 0; mt < 4; mt++)
#pragma unroll
                for (int nt = 0; nt < 4; nt++)
                    mma_f16(acc[mt][nt], afr[mt], bfr[nt]);
        }

        // 2-stage ring: chunk c+2 overwrites the stage just read.
        if (c + 2 < nch) {
            __syncthreads();
            ISSUE_CHUNK(c + 2, s);
        }
    }

    // Epilogue: bias, store half2 (intermediate) or float2 (final)
    const int c2 = cq << 1;
#pragma unroll
    for (int nt = 0; nt < 4; nt++) {
        const int gn = n0 + warp_n * 32 + nt * 8 + c2;
        const float b0 = bias[gn], b1 = bias[gn + 1];
#pragma unroll
        for (int mt = 0; mt < 4; mt++) {
            const int gm = m0 + warp_m * 64 + mt * 16 + r;
            float x0 = acc[mt][nt][0] + b0, y0 = acc[mt][nt][1] + b1;
            float x1 = acc[mt][nt][2] + b0, y1 = acc[mt][nt][3] + b1;
            if (half_out) {
                __half* Ch = (__half*)Cout;
                *(uint32_t*)&Ch[(size_t)gm * Nt + gn]       = pack_h2(x0, y0);
                *(uint32_t*)&Ch[(size_t)(gm + 8) * Nt + gn] = pack_h2(x1, y1);
            } else {
                float* Cf = (float*)Cout;
                *(float2*)&Cf[(size_t)gm * Nt + gn]       = make_float2(x0, y0);
                *(float2*)&Cf[(size_t)(gm + 8) * Nt + gn] = make_float2(x1, y1);
            }
        }
    }
#undef ISSUE_CHUNK
}

// ===========================================================================
// Flash attention, fp16 (R13, trailing barrier removed -- safe: all reads of
// stage kt%3 finish before any thread passes the top barrier of iter kt+1,
// which precedes the distance-2 issue overwriting that stage).
// mma.m16n8k16, 32-query warps, cp.async 3-stage K/V ring, ldmatrix Q/K,
// ldmatrix.trans V, P packed straight from fp32 S registers.
// AQ=256, 256 threads = 8 warps x 32 rows. Pitch 72 halves.
// ===========================================================================
#define AQ      256
#define APH     72
#define KSTGH   (2 * 64 * APH)                // K+V one stage (halves)
#define OFF_KVH (AQ * APH)
#define ATTN_SMEM ((OFF_KVH + 3 * KSTGH) * 2) // 92160 B

__global__ __launch_bounds__(256, 1)
void attn_mma(const __half* __restrict__ qkv, __half* __restrict__ out)
{
    extern __shared__ __half smh[];
    const uint32_t smb = smem_u32(smh);
    const int t    = threadIdx.x;
    const int lane = t & 31;
    const int wid  = t >> 5;
    const int r    = lane >> 2;
    const int cq   = lane & 3;
    const int g    = lane >> 3;
    const int j    = lane & 7;
    const int q0   = blockIdx.x * AQ;
    const int b    = blockIdx.y >> 4;
    const int h    = blockIdx.y & 15;
    const int rs   = 3 * C_DIM;

    const __half* qb = qkv + ((size_t)(b * NSEQ + q0) * 3) * C_DIM + h * HDIM;
    const __half* kb = qkv + ((size_t)(b * NSEQ) * 3 + 1) * C_DIM + h * HDIM;
    const __half* vb = qkv + ((size_t)(b * NSEQ) * 3 + 2) * C_DIM + h * HDIM;

    const int wrow = wid * 32;   // warp's query-row base (32 rows)

    const uint32_t q_lane = (uint32_t)(((wrow + (g & 1) * 8 + j) * APH
                                        + (g >> 1) * 8) * 2);
    const uint32_t k_lane = (uint32_t)((((g & 1) * 8 + j) * APH
                                        + (g >> 1) * 8) * 2);

    // staging: rows of 64 halves = 8 x 16B chunks
    const int srow = t >> 3;              // 0..31
    const int sc8  = (t & 7) << 3;        // half offset 0..56

    // ---- Q via cp.async (group 0): 256 rows -> 8 per thread ----
#pragma unroll
    for (int p = 0; p < 8; p++) {
        int row = srow + p * 32;
        CP16(smb + (uint32_t)((row * APH + sc8) * 2), qb + (size_t)row * rs + sc8);
    }
    CP_COMMIT();

#define ISSUE_KV(kt, s)                                                        \
    {                                                                          \
        const __half* kn = kb + (size_t)((kt) * 64) * rs;                      \
        const __half* vn = vb + (size_t)((kt) * 64) * rs;                      \
        const uint32_t sb = smb + (uint32_t)((OFF_KVH + (s) * KSTGH) * 2);     \
        _Pragma("unroll")                                                      \
        for (int p = 0; p < 2; p++) {                                          \
            int row = srow + p * 32;                                           \
            CP16(sb + (uint32_t)((row * APH + sc8) * 2),                       \
                 kn + (size_t)row * rs + sc8);                                 \
            CP16(sb + (uint32_t)((64 * APH + row * APH + sc8) * 2),            \
                 vn + (size_t)row * rs + sc8);                                 \
        }                                                                      \
        CP_COMMIT();                                                           \
    }

    ISSUE_KV(0, 0);
    ISSUE_KV(1, 1);

    float o_[2][8][4];
#pragma unroll
    for (int mt = 0; mt < 2; mt++)
#pragma unroll
        for (int nt = 0; nt < 8; nt++)
#pragma unroll
            for (int e = 0; e < 4; e++) o_[mt][nt][e] = 0.f;
    float m_r[2][2], l_r[2][2];
#pragma unroll
    for (int mt = 0; mt < 2; mt++) {
        m_r[mt][0] = -1e30f; m_r[mt][1] = -1e30f;
        l_r[mt][0] = 0.f;    l_r[mt][1] = 0.f;
    }

    const int NT = NSEQ / 64;
    int stage = 0;
    for (int kt = 0; kt < NT; kt++) {
        if (kt + 1 < NT) CP_WAIT1(); else CP_WAIT0();
        __syncthreads();
        if (kt + 2 < NT) {
            int ns = stage + 2; if (ns >= 3) ns -= 3;
            ISSUE_KV(kt + 2, ns);
        }

        const uint32_t kbase = smb + (uint32_t)((OFF_KVH + stage * KSTGH) * 2);
        const uint32_t vbase = kbase + (uint32_t)(64 * APH * 2);

        // ---- S = Q @ K^T (warp: 32 rows x 64 cols), 4 k16-steps over d ----
        float s_[2][8][4];
#pragma unroll
        for (int mt = 0; mt < 2; mt++)
#pragma unroll
            for (int nt = 0; nt < 8; nt++)
#pragma unroll
                for (int e = 0; e < 4; e++) s_[mt][nt][e] = 0.f;

#pragma unroll
        for (int ks = 0; ks < 4; ks++) {
            uint32_t aq[2][4];
            ldsm_x4(smb + q_lane + (uint32_t)(ks * 32), aq[0]);
            ldsm_x4(smb + q_lane + (uint32_t)(16 * APH * 2 + ks * 32), aq[1]);
#pragma unroll
            for (int p = 0; p < 4; p++) {
                uint32_t qv[4];
                ldsm_x4(kbase + k_lane + (uint32_t)((p * 16 * APH) * 2 + ks * 32), qv);
                uint32_t b0[2] = {qv[0], qv[2]};
                uint32_t b1[2] = {qv[1], qv[3]};
                mma_f16(s_[0][2 * p],     aq[0], b0);
                mma_f16(s_[0][2 * p + 1], aq[0], b1);
                mma_f16(s_[1][2 * p],     aq[1], b0);
                mma_f16(s_[1][2 * p + 1], aq[1], b1);
            }
        }

        // ---- online softmax (per mt: rows r, r+8; reduce over c-quad) ----
#pragma unroll
        for (int mt = 0; mt < 2; mt++) {
            float ml0 = -1e30f, ml1 = -1e30f;
#pragma unroll
            for (int nt = 0; nt < 8; nt++) {
                s_[mt][nt][0] *= ATT_SCALE; s_[mt][nt][1] *= ATT_SCALE;
                s_[mt][nt][2] *= ATT_SCALE; s_[mt][nt][3] *= ATT_SCALE;
                ml0 = fmaxf(ml0, fmaxf(s_[mt][nt][0], s_[mt][nt][1]));
                ml1 = fmaxf(ml1, fmaxf(s_[mt][nt][2], s_[mt][nt][3]));
            }
            ml0 = fmaxf(ml0, __shfl_xor_sync(0xffffffffu, ml0, 1));
            ml0 = fmaxf(ml0, __shfl_xor_sync(0xffffffffu, ml0, 2));
            ml1 = fmaxf(ml1, __shfl_xor_sync(0xffffffffu, ml1, 1));
            ml1 = fmaxf(ml1, __shfl_xor_sync(0xffffffffu, ml1, 2));

            float mn0 = fmaxf(m_r[mt][0], ml0), mn1 = fmaxf(m_r[mt][1], ml1);
            float cr0 = __expf(m_r[mt][0] - mn0), cr1 = __expf(m_r[mt][1] - mn1);
            m_r[mt][0] = mn0; m_r[mt][1] = mn1;

            float rs0 = 0.f, rs1 = 0.f;
#pragma unroll
            for (int nt = 0; nt < 8; nt++) {
                s_[mt][nt][0] = __expf(s_[mt][nt][0] - mn0);
                s_[mt][nt][1] = __expf(s_[mt][nt][1] - mn0);
                s_[mt][nt][2] = __expf(s_[mt][nt][2] - mn1);
                s_[mt][nt][3] = __expf(s_[mt][nt][3] - mn1);
                rs0 += s_[mt][nt][0] + s_[mt][nt][1];
                rs1 += s_[mt][nt][2] + s_[mt][nt][3];
            }
            rs0 += __shfl_xor_sync(0xffffffffu, rs0, 1);
            rs0 += __shfl_xor_sync(0xffffffffu, rs0, 2);
            rs1 += __shfl_xor_sync(0xffffffffu, rs1, 1);
            rs1 += __shfl_xor_sync(0xffffffffu, rs1, 2);
            l_r[mt][0] = l_r[mt][0] * cr0 + rs0;
            l_r[mt][1] = l_r[mt][1] * cr1 + rs1;

#pragma unroll
            for (int nt = 0; nt < 8; nt++) {
                o_[mt][nt][0] *= cr0; o_[mt][nt][1] *= cr0;
                o_[mt][nt][2] *= cr1; o_[mt][nt][3] *= cr1;
            }
        }

        // ---- O += P @ V, 4 k16-steps over keys; P from registers ----
#pragma unroll
        for (int ks = 0; ks < 4; ks++) {
            uint32_t a0[4], a1[4];
            a0[0] = pack_h2(s_[0][2 * ks][0],     s_[0][2 * ks][1]);
            a0[1] = pack_h2(s_[0][2 * ks][2],     s_[0][2 * ks][3]);
            a0[2] = pack_h2(s_[0][2 * ks + 1][0], s_[0][2 * ks + 1][1]);
            a0[3] = pack_h2(s_[0][2 * ks + 1][2], s_[0][2 * ks + 1][3]);
            a1[0] = pack_h2(s_[1][2 * ks][0],     s_[1][2 * ks][1]);
            a1[1] = pack_h2(s_[1][2 * ks][2],     s_[1][2 * ks][3]);
            a1[2] = pack_h2(s_[1][2 * ks + 1][0], s_[1][2 * ks + 1][1]);
            a1[3] = pack_h2(s_[1][2 * ks + 1][2], s_[1][2 * ks + 1][3]);
#pragma unroll
            for (int p = 0; p < 4; p++) {
                uint32_t qv[4];
                ldsm_x4t(vbase + k_lane
                         + (uint32_t)((ks * 16 * APH + p * 16) * 2), qv);
                uint32_t b0[2] = {qv[0], qv[1]};
                uint32_t b1[2] = {qv[2], qv[3]};
                mma_f16(o_[0][2 * p],     a0, b0);
                mma_f16(o_[0][2 * p + 1], a0, b1);
                mma_f16(o_[1][2 * p],     a1, b0);
                mma_f16(o_[1][2 * p + 1], a1, b1);
            }
        }

        if (++stage == 3) stage = 0;
        // trailing barrier removed (top-of-loop barrier suffices; ring dist 2)
    }

    // ---- epilogue: normalize, store half2 to [4096,1024] ----
#pragma unroll
    for (int mt = 0; mt < 2; mt++) {
        const float i0 = 1.f / l_r[mt][0], i1 = 1.f / l_r[mt][1];
        const int row0 = b * NSEQ + q0 + wrow + mt * 16 + r;
#pragma unroll
        for (int nt = 0; nt < 8; nt++) {
            const int col = h * HDIM + nt * 8 + 2 * cq;
            *(uint32_t*)&out[(size_t)row0 * C_DIM + col] =
                pack_h2(o_[mt][nt][0] * i0, o_[mt][nt][1] * i0);
            *(uint32_t*)&out[(size_t)(row0 + 8) * C_DIM + col] =
                pack_h2(o_[mt][nt][2] * i1, o_[mt][nt][3] * i1);
        }
    }
#undef ISSUE_KV
}

// ---------------------------------------------------------------------------
extern "C" void kernel_launch(void* const* d_in, const int* in_sizes, int n_in,
                              void* d_out, int out_size)
{
    const float* x      = (const float*)d_in[0];
    const float* w_qkv  = (const float*)d_in[1];
    const float* b_qkv  = (const float*)d_in[2];
    const float* w_proj = (const float*)d_in[3];
    const float* b_proj = (const float*)d_in[4];
    float* out = (float*)d_out;

    __half *qkv_s, *att_s, *xh, *wqh, *wph;
    cudaGetSymbolAddress((void**)&qkv_s, g_qkvh);
    cudaGetSymbolAddress((void**)&att_s, g_atth);
    cudaGetSymbolAddress((void**)&xh,    g_xh);
    cudaGetSymbolAddress((void**)&wqh,   g_wqkvh);
    cudaGetSymbolAddress((void**)&wph,   g_wprojh);

    cudaFuncSetAttribute(gemm_mma_f16, cudaFuncAttributeMaxDynamicSharedMemorySize, GEMM_SMEM);
    cudaFuncSetAttribute(attn_mma, cudaFuncAttributeMaxDynamicSharedMemorySize, ATTN_SMEM);

    // 0) Pre-convert inputs to fp16 (single merged launch)
    cvt3_f16<<<1184, 256>>>(x, xh, ROWS * C_DIM / 4,
                            w_qkv, wqh, 3 * C_DIM * C_DIM / 4,
                            w_proj, wph, C_DIM * C_DIM / 4);

    // 1) QKV projection -> fp16 [4096,3072]
    dim3 g1(3 * C_DIM / 128, ROWS / 128);
    gemm_mma_f16<<<g1, 256, GEMM_SMEM>>>(xh, wqh, b_qkv, qkv_s,
                                         ROWS, 3 * C_DIM, C_DIM, 1);

    // 2) Fused attention -> fp16 [4096,1024]
    dim3 g2(NSEQ / AQ, BATCH * NHEADS);
    attn_mma<<<g2, 256, ATTN_SMEM>>>(qkv_s, att_s);

    // 3) Output projection -> fp32 out
    dim3 g3(C_DIM / 128, ROWS / 128);
    gemm_mma_f16<<<g3, 256, GEMM_SMEM>>>(att_s, wph, b_proj, out,
                                         ROWS, C_DIM, C_DIM, 0);
}